// round 1
// baseline (speedup 1.0000x reference)
#include <cuda_runtime.h>
#include <math.h>

#define BB 2
#define NN 2048
#define DD 1024
#define HH 16
#define HD 64

// -------- scratch (static device arrays; no allocation) --------
__device__ float g_q[(size_t)BB*HH*NN*HD];
__device__ float g_k[(size_t)BB*HH*NN*HD];
__device__ float g_v[(size_t)BB*HH*NN*HD];
__device__ float g_ctx[(size_t)BB*NN*DD];

// ============================================================
// GEMM: C = A[M,K] * W[N,K]^T (+bias).  M=4096, N=1024, K=1024.
// mode 0: scatter into head layout [(b*H+h)*NN + i]*HD + c  (for Q/K/V)
// mode 1: row-major C[m*DD+n] + bias  (final projection)
// 64x64 block tile, 256 threads, 4x4 per-thread micro tile, BK=16.
// ============================================================
__global__ __launch_bounds__(256) void gemm_nt_kernel(
    const float* __restrict__ A, const float* __restrict__ W,
    const float* __restrict__ bias, float* __restrict__ C, int mode)
{
    __shared__ float As[16*68];
    __shared__ float Bs[16*68];

    const int tid = threadIdx.x;
    const int m0 = blockIdx.y * 64;
    const int n0 = blockIdx.x * 64;
    const int lr = tid >> 2;          // 0..63 row within tile
    const int ls = (tid & 3) * 4;     // k offset 0,4,8,12
    const int ty = tid >> 4;          // 0..15
    const int tx = tid & 15;          // 0..15

    float acc[4][4];
#pragma unroll
    for (int u = 0; u < 4; u++)
#pragma unroll
        for (int v = 0; v < 4; v++) acc[u][v] = 0.f;

    for (int k0 = 0; k0 < DD; k0 += 16) {
        float4 av = *(const float4*)&A[(size_t)(m0 + lr) * DD + k0 + ls];
        float4 bv = *(const float4*)&W[(size_t)(n0 + lr) * DD + k0 + ls];
        As[(ls + 0) * 68 + lr] = av.x;
        As[(ls + 1) * 68 + lr] = av.y;
        As[(ls + 2) * 68 + lr] = av.z;
        As[(ls + 3) * 68 + lr] = av.w;
        Bs[(ls + 0) * 68 + lr] = bv.x;
        Bs[(ls + 1) * 68 + lr] = bv.y;
        Bs[(ls + 2) * 68 + lr] = bv.z;
        Bs[(ls + 3) * 68 + lr] = bv.w;
        __syncthreads();
#pragma unroll
        for (int kk = 0; kk < 16; kk++) {
            float4 a = *(const float4*)&As[kk * 68 + ty * 4];
            float4 b = *(const float4*)&Bs[kk * 68 + tx * 4];
            float ar[4] = {a.x, a.y, a.z, a.w};
            float br[4] = {b.x, b.y, b.z, b.w};
#pragma unroll
            for (int u = 0; u < 4; u++)
#pragma unroll
                for (int v = 0; v < 4; v++) acc[u][v] += ar[u] * br[v];
        }
        __syncthreads();
    }

    if (mode == 0) {
        // scatter into [B,H,N,HD]
#pragma unroll
        for (int u = 0; u < 4; u++) {
            int m = m0 + ty * 4 + u;
            int b = m >> 11;          // /NN
            int i = m & (NN - 1);
#pragma unroll
            for (int v = 0; v < 4; v++) {
                int n = n0 + tx * 4 + v;
                int h = n >> 6;
                int c = n & 63;
                C[((size_t)(b * HH + h) * NN + i) * HD + c] = acc[u][v];
            }
        }
    } else {
#pragma unroll
        for (int u = 0; u < 4; u++) {
            int m = m0 + ty * 4 + u;
            float4 o;
            int n = n0 + tx * 4;
            o.x = acc[u][0] + bias[n + 0];
            o.y = acc[u][1] + bias[n + 1];
            o.z = acc[u][2] + bias[n + 2];
            o.w = acc[u][3] + bias[n + 3];
            *(float4*)&C[(size_t)m * DD + n] = o;
        }
    }
}

// ============================================================
// Attention with adaptive-temperature softmax.
// Grid (N/64, H, B), 256 threads. Two passes over causal key tiles.
// ============================================================
__device__ __forceinline__ float warpMax(float v) {
#pragma unroll
    for (int o = 16; o > 0; o >>= 1) v = fmaxf(v, __shfl_xor_sync(0xffffffffu, v, o));
    return v;
}
__device__ __forceinline__ float warpSum(float v) {
#pragma unroll
    for (int o = 16; o > 0; o >>= 1) v += __shfl_xor_sync(0xffffffffu, v, o);
    return v;
}

#define ST 68  // padded row stride for 64-wide tiles
#define MASKV (-1e30f)

__device__ __forceinline__ void load_tile64(float* dst, const float* __restrict__ src, int tid) {
    // src: row-major 64x64 contiguous; dst: stride ST
    int r = tid >> 2;
    int s4 = (tid & 3) * 16;
    const float4* s = (const float4*)(src + (size_t)r * 64 + s4);
    float4* d = (float4*)(dst + r * ST + s4);
    d[0] = s[0]; d[1] = s[1]; d[2] = s[2]; d[3] = s[3];
}

__global__ __launch_bounds__(256) void attn_kernel(float* __restrict__ gO)
{
    extern __shared__ float sm[];
    float* sQ = sm;                 // 64*ST
    float* sK = sQ + 64 * ST;
    float* sV = sK + 64 * ST;
    float* sS = sV + 64 * ST;       // scores / probs
    float* sBeta = sS + 64 * ST;    // 64
    float* sMp   = sBeta + 64;      // 64 (beta*m)
    float* sL    = sMp + 64;        // 64 (l')

    const int qt = blockIdx.x;
    const int h  = blockIdx.y;
    const int b  = blockIdx.z;
    const int tid = threadIdx.x;
    const int ty = tid >> 4, tx = tid & 15;
    const int w = tid >> 5, lane = tid & 31;
    const int i0 = ty * 4, j0 = tx * 4;
    const int q0 = qt * 64;

    const size_t headoff = (size_t)(b * HH + h) * NN * HD;
    const float* Qh = g_q + headoff;
    const float* Kh = g_k + headoff;
    const float* Vh = g_v + headoff;

    load_tile64(sQ, Qh + (size_t)q0 * HD, tid);

    // ---------- pass A: m, l, t(=sum e*s) per row ----------
    float mrow[8], lrow[8], trow[8];
#pragma unroll
    for (int rr = 0; rr < 8; rr++) { mrow[rr] = MASKV; lrow[rr] = 0.f; trow[rr] = 0.f; }

    for (int kt = 0; kt <= qt; kt++) {
        __syncthreads();
        load_tile64(sK, Kh + (size_t)kt * 64 * HD, tid);
        __syncthreads();

        float acc[4][4];
#pragma unroll
        for (int u = 0; u < 4; u++)
#pragma unroll
            for (int v = 0; v < 4; v++) acc[u][v] = 0.f;
#pragma unroll
        for (int d = 0; d < 64; d += 4) {
            float4 av[4], bv[4];
#pragma unroll
            for (int u = 0; u < 4; u++) av[u] = *(const float4*)&sQ[(i0 + u) * ST + d];
#pragma unroll
            for (int v = 0; v < 4; v++) bv[v] = *(const float4*)&sK[(j0 + v) * ST + d];
#pragma unroll
            for (int u = 0; u < 4; u++)
#pragma unroll
                for (int v = 0; v < 4; v++)
                    acc[u][v] += av[u].x * bv[v].x + av[u].y * bv[v].y
                               + av[u].z * bv[v].z + av[u].w * bv[v].w;
        }
#pragma unroll
        for (int u = 0; u < 4; u++) {
            int ig = q0 + i0 + u;
#pragma unroll
            for (int v = 0; v < 4; v++) {
                int jg = kt * 64 + j0 + v;
                float s = acc[u][v] * 0.125f;   // 1/sqrt(64)
                if (jg > ig) s = MASKV;
                sS[(i0 + u) * ST + j0 + v] = s;
            }
        }
        __syncthreads();

        // per-row online update (warp w owns rows w*8..w*8+7)
#pragma unroll
        for (int rr = 0; rr < 8; rr++) {
            int r = w * 8 + rr;
            float x1 = sS[r * ST + lane];
            float x2 = sS[r * ST + 32 + lane];
            float mt = warpMax(fmaxf(x1, x2));
            float mnew = fmaxf(mrow[rr], mt);
            float e1 = expf(x1 - mnew);
            float e2 = expf(x2 - mnew);
            float se = warpSum(e1 + e2);
            float st = warpSum(e1 * x1 + e2 * x2);
            float corr = expf(mrow[rr] - mnew);
            lrow[rr] = lrow[rr] * corr + se;
            trow[rr] = trow[rr] * corr + st;
            mrow[rr] = mnew;
        }
    }

    // entropy -> beta per row
#pragma unroll
    for (int rr = 0; rr < 8; rr++) {
        int r = w * 8 + rr;
        float l = lrow[rr], m = mrow[rr], t = trow[rr];
        float ent = logf(l) + m - t / l;
        float beta = 1.f;
        if (ent > 0.5f) {
            float poly = ((((-0.037f * ent + 0.481f) * ent - 2.3f) * ent + 4.917f) * ent - 1.791f);
            beta = fmaxf(poly, 1.f);
        }
        if (lane == 0) { sBeta[r] = beta; sMp[r] = beta * m; }
    }
    __syncthreads();

    float betas[4], mps[4];
#pragma unroll
    for (int u = 0; u < 4; u++) { betas[u] = sBeta[i0 + u]; mps[u] = sMp[i0 + u]; }

    // ---------- pass B: p = exp(beta*s - beta*m), O = P*V, l' ----------
    float O[4][4];
#pragma unroll
    for (int u = 0; u < 4; u++)
#pragma unroll
        for (int v = 0; v < 4; v++) O[u][v] = 0.f;
    float l2[8];
#pragma unroll
    for (int rr = 0; rr < 8; rr++) l2[rr] = 0.f;

    for (int kt = 0; kt <= qt; kt++) {
        __syncthreads();
        load_tile64(sK, Kh + (size_t)kt * 64 * HD, tid);
        load_tile64(sV, Vh + (size_t)kt * 64 * HD, tid);
        __syncthreads();

        float acc[4][4];
#pragma unroll
        for (int u = 0; u < 4; u++)
#pragma unroll
            for (int v = 0; v < 4; v++) acc[u][v] = 0.f;
#pragma unroll
        for (int d = 0; d < 64; d += 4) {
            float4 av[4], bv[4];
#pragma unroll
            for (int u = 0; u < 4; u++) av[u] = *(const float4*)&sQ[(i0 + u) * ST + d];
#pragma unroll
            for (int v = 0; v < 4; v++) bv[v] = *(const float4*)&sK[(j0 + v) * ST + d];
#pragma unroll
            for (int u = 0; u < 4; u++)
#pragma unroll
                for (int v = 0; v < 4; v++)
                    acc[u][v] += av[u].x * bv[v].x + av[u].y * bv[v].y
                               + av[u].z * bv[v].z + av[u].w * bv[v].w;
        }
#pragma unroll
        for (int u = 0; u < 4; u++) {
            int ig = q0 + i0 + u;
#pragma unroll
            for (int v = 0; v < 4; v++) {
                int jg = kt * 64 + j0 + v;
                float s = acc[u][v] * 0.125f;
                if (jg > ig) s = MASKV;
                float p = expf(betas[u] * s - mps[u]);
                sS[(i0 + u) * ST + j0 + v] = p;
            }
        }
        __syncthreads();

        // row sums of P
#pragma unroll
        for (int rr = 0; rr < 8; rr++) {
            int r = w * 8 + rr;
            l2[rr] += warpSum(sS[r * ST + lane] + sS[r * ST + 32 + lane]);
        }
        // O += P * V
#pragma unroll 4
        for (int j = 0; j < 64; j++) {
            float4 vv = *(const float4*)&sV[j * ST + j0];
            float pv[4];
#pragma unroll
            for (int u = 0; u < 4; u++) pv[u] = sS[(i0 + u) * ST + j];
#pragma unroll
            for (int u = 0; u < 4; u++) {
                O[u][0] += pv[u] * vv.x;
                O[u][1] += pv[u] * vv.y;
                O[u][2] += pv[u] * vv.z;
                O[u][3] += pv[u] * vv.w;
            }
        }
    }

#pragma unroll
    for (int rr = 0; rr < 8; rr++)
        if (lane == 0) sL[w * 8 + rr] = l2[rr];
    __syncthreads();

    // write ctx[b, q0+i, h*64 + d]
#pragma unroll
    for (int u = 0; u < 4; u++) {
        float inv = 1.f / sL[i0 + u];
        float4 o;
        o.x = O[u][0] * inv; o.y = O[u][1] * inv;
        o.z = O[u][2] * inv; o.w = O[u][3] * inv;
        size_t row = (size_t)(b * NN + q0 + i0 + u) * DD + h * HD + j0;
        *(float4*)&gO[row] = o;
    }
}

// ============================================================
extern "C" void kernel_launch(void* const* d_in, const int* in_sizes, int n_in,
                              void* d_out, int out_size)
{
    const float* x  = (const float*)d_in[0];
    const float* Wq = (const float*)d_in[1];
    const float* Wk = (const float*)d_in[2];
    const float* Wv = (const float*)d_in[3];
    const float* Wo = (const float*)d_in[4];
    const float* bo = (const float*)d_in[5];
    float* out = (float*)d_out;

    float *qp, *kp, *vp, *ctxp;
    cudaGetSymbolAddress((void**)&qp,   g_q);
    cudaGetSymbolAddress((void**)&kp,   g_k);
    cudaGetSymbolAddress((void**)&vp,   g_v);
    cudaGetSymbolAddress((void**)&ctxp, g_ctx);

    const int smem = (4 * 64 * ST + 3 * 64) * (int)sizeof(float);  // 70400 B
    cudaFuncSetAttribute(attn_kernel, cudaFuncAttributeMaxDynamicSharedMemorySize, smem);

    dim3 ggrid(DD / 64, (BB * NN) / 64);   // (16, 64)
    gemm_nt_kernel<<<ggrid, 256>>>(x, Wq, nullptr, qp, 0);
    gemm_nt_kernel<<<ggrid, 256>>>(x, Wk, nullptr, kp, 0);
    gemm_nt_kernel<<<ggrid, 256>>>(x, Wv, nullptr, vp, 0);

    dim3 agrid(NN / 64, HH, BB);           // (32, 16, 2)
    attn_kernel<<<agrid, 256, smem>>>(ctxp);

    gemm_nt_kernel<<<ggrid, 256>>>(ctxp, Wo, bo, out, 1);
}